// round 2
// baseline (speedup 1.0000x reference)
#include <cuda_runtime.h>
#include <cuda_bf16.h>

#define NPTS   120000
#define BB     4
#define TOTPTS (BB * NPTS)
#define HH     128
#define WW     128
#define HW     (HH * WW)
#define FEAT   128

// Folded-parameter layout inside g_params / shared memory (float offsets)
#define OFF_W1T 0        // [4][64]    transposed, BN-folded
#define OFF_C1  256      // [64]
#define OFF_C2  320      // [128]
#define OFF_C3  448      // [128]
#define OFF_W2T 576      // [64][128]  transposed, BN-folded
#define OFF_W3T 8768     // [128][128] transposed, BN-folded
#define NPARAM  25152
#define ACT_OFF NPARAM   // per-thread activation columns: [128 rows][128 threads]
#define SMEM_FLOATS (NPARAM + 128 * 128)
#define SMEM_BYTES  (SMEM_FLOATS * 4)

__device__ __align__(16) float g_params[NPARAM];

// ---------------------------------------------------------------------------
// Prep: fold BN (scale/shift) into weights & biases, transpose to [i][o].
// ---------------------------------------------------------------------------
__global__ void prep_kernel(
    const float* __restrict__ W1, const float* __restrict__ b1,
    const float* __restrict__ g1, const float* __restrict__ be1,
    const float* __restrict__ m1, const float* __restrict__ v1,
    const float* __restrict__ W2, const float* __restrict__ b2,
    const float* __restrict__ g2, const float* __restrict__ be2,
    const float* __restrict__ m2, const float* __restrict__ v2,
    const float* __restrict__ W3, const float* __restrict__ b3,
    const float* __restrict__ g3, const float* __restrict__ be3,
    const float* __restrict__ m3, const float* __restrict__ v3)
{
    const int t = threadIdx.x;
    for (int o = t; o < 64; o += blockDim.x) {
        float s = g1[o] * rsqrtf(v1[o] + 1e-5f);
        g_params[OFF_C1 + o] = (b1[o] - m1[o]) * s + be1[o];
        for (int i = 0; i < 4; i++)
            g_params[OFF_W1T + i * 64 + o] = W1[o * 4 + i] * s;
    }
    for (int o = t; o < 128; o += blockDim.x) {
        float s2 = g2[o] * rsqrtf(v2[o] + 1e-5f);
        g_params[OFF_C2 + o] = (b2[o] - m2[o]) * s2 + be2[o];
        for (int i = 0; i < 64; i++)
            g_params[OFF_W2T + i * 128 + o] = W2[o * 64 + i] * s2;
        float s3 = g3[o] * rsqrtf(v3[o] + 1e-5f);
        g_params[OFF_C3 + o] = (b3[o] - m3[o]) * s3 + be3[o];
        for (int i = 0; i < 128; i++)
            g_params[OFF_W3T + i * 128 + o] = W3[o * 128 + i] * s3;
    }
}

// ---------------------------------------------------------------------------
// Main: one thread = one point. Weights in SMEM (broadcast LDS.128),
// dynamically-indexed activations in a private SMEM column, 128 accumulators
// in registers. Scatter-max via int-aliased atomicMax (all values >= 0).
// ---------------------------------------------------------------------------
__global__ __launch_bounds__(128, 1)
void point_kernel(const float* __restrict__ points, float* __restrict__ out)
{
    extern __shared__ float sm[];
    const int tid = threadIdx.x;

    // Cooperative copy of folded params into SMEM (6288 float4)
    {
        const float4* src = (const float4*)g_params;
        float4* dst = (float4*)sm;
        for (int k = tid; k < NPARAM / 4; k += 128) dst[k] = src[k];
    }
    __syncthreads();

    const int g = blockIdx.x * 128 + tid;
    const float4 p = ((const float4*)points)[g];

    const float xn = (p.x + 50.0f) / 100.0f;
    const float yn = (p.y + 50.0f) / 100.0f;
    if (!(xn >= 0.0f && xn <= 1.0f && yn >= 0.0f && yn <= 1.0f)) return;
    const int gx = min(WW - 1, (int)(xn * (float)(WW - 1)));
    const int gy = min(HH - 1, (int)(yn * (float)(HH - 1)));
    const int b  = g / NPTS;

    float* acts = sm + ACT_OFF + tid;   // column stride 128 floats, conflict-free
    const float pa[4] = { p.x, p.y, p.z, p.w };

    // ---- Layer 1: 4 -> 64 ----
    #pragma unroll
    for (int o = 0; o < 64; o += 4) {
        float4 acc1 = *(const float4*)(sm + OFF_C1 + o);
        #pragma unroll
        for (int i = 0; i < 4; i++) {
            const float4 w = *(const float4*)(sm + OFF_W1T + i * 64 + o);
            acc1.x = fmaf(w.x, pa[i], acc1.x);
            acc1.y = fmaf(w.y, pa[i], acc1.y);
            acc1.z = fmaf(w.z, pa[i], acc1.z);
            acc1.w = fmaf(w.w, pa[i], acc1.w);
        }
        acts[(o + 0) * 128] = fmaxf(acc1.x, 0.0f);
        acts[(o + 1) * 128] = fmaxf(acc1.y, 0.0f);
        acts[(o + 2) * 128] = fmaxf(acc1.z, 0.0f);
        acts[(o + 3) * 128] = fmaxf(acc1.w, 0.0f);
    }

    float4 acc[32];

    // ---- Layer 2: 64 -> 128 ----
    {
        const float4* c2v = (const float4*)(sm + OFF_C2);
        #pragma unroll
        for (int o4 = 0; o4 < 32; o4++) acc[o4] = c2v[o4];
        const float4* W2T4 = (const float4*)(sm + OFF_W2T);
        #pragma unroll 2
        for (int i = 0; i < 64; i++) {
            const float a = acts[i * 128];
            #pragma unroll
            for (int o4 = 0; o4 < 32; o4++) {
                const float4 w = W2T4[i * 32 + o4];
                acc[o4].x = fmaf(w.x, a, acc[o4].x);
                acc[o4].y = fmaf(w.y, a, acc[o4].y);
                acc[o4].z = fmaf(w.z, a, acc[o4].z);
                acc[o4].w = fmaf(w.w, a, acc[o4].w);
            }
        }
        #pragma unroll
        for (int o4 = 0; o4 < 32; o4++) {
            acts[(4 * o4 + 0) * 128] = fmaxf(acc[o4].x, 0.0f);
            acts[(4 * o4 + 1) * 128] = fmaxf(acc[o4].y, 0.0f);
            acts[(4 * o4 + 2) * 128] = fmaxf(acc[o4].z, 0.0f);
            acts[(4 * o4 + 3) * 128] = fmaxf(acc[o4].w, 0.0f);
        }
    }

    // ---- Layer 3: 128 -> 128 ----
    {
        const float4* c3v = (const float4*)(sm + OFF_C3);
        #pragma unroll
        for (int o4 = 0; o4 < 32; o4++) acc[o4] = c3v[o4];
        const float4* W3T4 = (const float4*)(sm + OFF_W3T);
        #pragma unroll 2
        for (int i = 0; i < 128; i++) {
            const float a = acts[i * 128];
            #pragma unroll
            for (int o4 = 0; o4 < 32; o4++) {
                const float4 w = W3T4[i * 32 + o4];
                acc[o4].x = fmaf(w.x, a, acc[o4].x);
                acc[o4].y = fmaf(w.y, a, acc[o4].y);
                acc[o4].z = fmaf(w.z, a, acc[o4].z);
                acc[o4].w = fmaf(w.w, a, acc[o4].w);
            }
        }
    }

    // ---- Scatter-max into (B, FEAT, H, W) ----
    int* ob = (int*)out + b * (FEAT * HW) + gy * WW + gx;
    #pragma unroll
    for (int o4 = 0; o4 < 32; o4++) {
        const float4 v = acc[o4];
        if (v.x > 0.0f) atomicMax(ob + (4 * o4 + 0) * HW, __float_as_int(v.x));
        if (v.y > 0.0f) atomicMax(ob + (4 * o4 + 1) * HW, __float_as_int(v.y));
        if (v.z > 0.0f) atomicMax(ob + (4 * o4 + 2) * HW, __float_as_int(v.z));
        if (v.w > 0.0f) atomicMax(ob + (4 * o4 + 3) * HW, __float_as_int(v.w));
    }
}

// ---------------------------------------------------------------------------
extern "C" void kernel_launch(void* const* d_in, const int* in_sizes, int n_in,
                              void* d_out, int out_size)
{
    const float* points = (const float*)d_in[0];

    // Output init: empty cells must be 0; all scattered values are >= 0.
    cudaMemsetAsync(d_out, 0, (size_t)out_size * sizeof(float), 0);

    prep_kernel<<<1, 256>>>(
        (const float*)d_in[1],  (const float*)d_in[2],  (const float*)d_in[3],
        (const float*)d_in[4],  (const float*)d_in[5],  (const float*)d_in[6],
        (const float*)d_in[7],  (const float*)d_in[8],  (const float*)d_in[9],
        (const float*)d_in[10], (const float*)d_in[11], (const float*)d_in[12],
        (const float*)d_in[13], (const float*)d_in[14], (const float*)d_in[15],
        (const float*)d_in[16], (const float*)d_in[17], (const float*)d_in[18]);

    cudaFuncSetAttribute(point_kernel,
                         cudaFuncAttributeMaxDynamicSharedMemorySize, SMEM_BYTES);
    point_kernel<<<TOTPTS / 128, 128, SMEM_BYTES>>>(points, (float*)d_out);
}

// round 3
// speedup vs baseline: 1.0009x; 1.0009x over previous
#include <cuda_runtime.h>
#include <cuda_bf16.h>

#define NPTS   120000
#define BB     4
#define TOTPTS (BB * NPTS)
#define HH     128
#define WW     128
#define HW     (HH * WW)
#define FEAT   128

// Folded-parameter layout inside g_params / shared memory (float offsets)
#define OFF_W1T 0        // [4][64]    transposed, BN-folded
#define OFF_C1  256      // [64]
#define OFF_C2  320      // [128]
#define OFF_C3  448      // [128]
#define OFF_W2T 576      // [64][128]  transposed, BN-folded
#define OFF_W3T 8768     // [128][128] transposed, BN-folded
#define NPARAM  25152
#define ACT_OFF NPARAM   // per-thread activation columns: [128 rows][128 threads]
#define SMEM_FLOATS (NPARAM + 128 * 128)
#define SMEM_BYTES  (SMEM_FLOATS * 4)

__device__ __align__(16) float g_params[NPARAM];

// ---------------------------------------------------------------------------
// Prep: fold BN (scale/shift) into weights & biases, transpose to [i][o].
// ---------------------------------------------------------------------------
__global__ void prep_kernel(
    const float* __restrict__ W1, const float* __restrict__ b1,
    const float* __restrict__ g1, const float* __restrict__ be1,
    const float* __restrict__ m1, const float* __restrict__ v1,
    const float* __restrict__ W2, const float* __restrict__ b2,
    const float* __restrict__ g2, const float* __restrict__ be2,
    const float* __restrict__ m2, const float* __restrict__ v2,
    const float* __restrict__ W3, const float* __restrict__ b3,
    const float* __restrict__ g3, const float* __restrict__ be3,
    const float* __restrict__ m3, const float* __restrict__ v3)
{
    const int t = threadIdx.x;
    for (int o = t; o < 64; o += blockDim.x) {
        float s = g1[o] * rsqrtf(v1[o] + 1e-5f);
        g_params[OFF_C1 + o] = (b1[o] - m1[o]) * s + be1[o];
        for (int i = 0; i < 4; i++)
            g_params[OFF_W1T + i * 64 + o] = W1[o * 4 + i] * s;
    }
    for (int o = t; o < 128; o += blockDim.x) {
        float s2 = g2[o] * rsqrtf(v2[o] + 1e-5f);
        g_params[OFF_C2 + o] = (b2[o] - m2[o]) * s2 + be2[o];
        for (int i = 0; i < 64; i++)
            g_params[OFF_W2T + i * 128 + o] = W2[o * 64 + i] * s2;
        float s3 = g3[o] * rsqrtf(v3[o] + 1e-5f);
        g_params[OFF_C3 + o] = (b3[o] - m3[o]) * s3 + be3[o];
        for (int i = 0; i < 128; i++)
            g_params[OFF_W3T + i * 128 + o] = W3[o * 128 + i] * s3;
    }
}

// ---------------------------------------------------------------------------
// Main: one thread = one point. Weights in SMEM (broadcast LDS.128),
// dynamically-indexed activations in a private SMEM column, 128 accumulators
// in registers. Scatter-max via int-aliased atomicMax (all values >= 0).
// ---------------------------------------------------------------------------
__global__ __launch_bounds__(128, 1)
void point_kernel(const float* __restrict__ points, float* __restrict__ out)
{
    extern __shared__ float sm[];
    const int tid = threadIdx.x;

    // Cooperative copy of folded params into SMEM (6288 float4)
    {
        const float4* src = (const float4*)g_params;
        float4* dst = (float4*)sm;
        for (int k = tid; k < NPARAM / 4; k += 128) dst[k] = src[k];
    }
    __syncthreads();

    const int g = blockIdx.x * 128 + tid;
    const float4 p = ((const float4*)points)[g];

    const float xn = (p.x + 50.0f) / 100.0f;
    const float yn = (p.y + 50.0f) / 100.0f;
    if (!(xn >= 0.0f && xn <= 1.0f && yn >= 0.0f && yn <= 1.0f)) return;
    const int gx = min(WW - 1, (int)(xn * (float)(WW - 1)));
    const int gy = min(HH - 1, (int)(yn * (float)(HH - 1)));
    const int b  = g / NPTS;

    float* acts = sm + ACT_OFF + tid;   // column stride 128 floats, conflict-free
    const float pa[4] = { p.x, p.y, p.z, p.w };

    // ---- Layer 1: 4 -> 64 ----
    #pragma unroll
    for (int o = 0; o < 64; o += 4) {
        float4 acc1 = *(const float4*)(sm + OFF_C1 + o);
        #pragma unroll
        for (int i = 0; i < 4; i++) {
            const float4 w = *(const float4*)(sm + OFF_W1T + i * 64 + o);
            acc1.x = fmaf(w.x, pa[i], acc1.x);
            acc1.y = fmaf(w.y, pa[i], acc1.y);
            acc1.z = fmaf(w.z, pa[i], acc1.z);
            acc1.w = fmaf(w.w, pa[i], acc1.w);
        }
        acts[(o + 0) * 128] = fmaxf(acc1.x, 0.0f);
        acts[(o + 1) * 128] = fmaxf(acc1.y, 0.0f);
        acts[(o + 2) * 128] = fmaxf(acc1.z, 0.0f);
        acts[(o + 3) * 128] = fmaxf(acc1.w, 0.0f);
    }

    float4 acc[32];

    // ---- Layer 2: 64 -> 128 ----
    {
        const float4* c2v = (const float4*)(sm + OFF_C2);
        #pragma unroll
        for (int o4 = 0; o4 < 32; o4++) acc[o4] = c2v[o4];
        const float4* W2T4 = (const float4*)(sm + OFF_W2T);
        #pragma unroll 2
        for (int i = 0; i < 64; i++) {
            const float a = acts[i * 128];
            #pragma unroll
            for (int o4 = 0; o4 < 32; o4++) {
                const float4 w = W2T4[i * 32 + o4];
                acc[o4].x = fmaf(w.x, a, acc[o4].x);
                acc[o4].y = fmaf(w.y, a, acc[o4].y);
                acc[o4].z = fmaf(w.z, a, acc[o4].z);
                acc[o4].w = fmaf(w.w, a, acc[o4].w);
            }
        }
        #pragma unroll
        for (int o4 = 0; o4 < 32; o4++) {
            acts[(4 * o4 + 0) * 128] = fmaxf(acc[o4].x, 0.0f);
            acts[(4 * o4 + 1) * 128] = fmaxf(acc[o4].y, 0.0f);
            acts[(4 * o4 + 2) * 128] = fmaxf(acc[o4].z, 0.0f);
            acts[(4 * o4 + 3) * 128] = fmaxf(acc[o4].w, 0.0f);
        }
    }

    // ---- Layer 3: 128 -> 128 ----
    {
        const float4* c3v = (const float4*)(sm + OFF_C3);
        #pragma unroll
        for (int o4 = 0; o4 < 32; o4++) acc[o4] = c3v[o4];
        const float4* W3T4 = (const float4*)(sm + OFF_W3T);
        #pragma unroll 2
        for (int i = 0; i < 128; i++) {
            const float a = acts[i * 128];
            #pragma unroll
            for (int o4 = 0; o4 < 32; o4++) {
                const float4 w = W3T4[i * 32 + o4];
                acc[o4].x = fmaf(w.x, a, acc[o4].x);
                acc[o4].y = fmaf(w.y, a, acc[o4].y);
                acc[o4].z = fmaf(w.z, a, acc[o4].z);
                acc[o4].w = fmaf(w.w, a, acc[o4].w);
            }
        }
    }

    // ---- Scatter-max into (B, FEAT, H, W) ----
    int* ob = (int*)out + b * (FEAT * HW) + gy * WW + gx;
    #pragma unroll
    for (int o4 = 0; o4 < 32; o4++) {
        const float4 v = acc[o4];
        if (v.x > 0.0f) atomicMax(ob + (4 * o4 + 0) * HW, __float_as_int(v.x));
        if (v.y > 0.0f) atomicMax(ob + (4 * o4 + 1) * HW, __float_as_int(v.y));
        if (v.z > 0.0f) atomicMax(ob + (4 * o4 + 2) * HW, __float_as_int(v.z));
        if (v.w > 0.0f) atomicMax(ob + (4 * o4 + 3) * HW, __float_as_int(v.w));
    }
}

// ---------------------------------------------------------------------------
extern "C" void kernel_launch(void* const* d_in, const int* in_sizes, int n_in,
                              void* d_out, int out_size)
{
    const float* points = (const float*)d_in[0];

    // Output init: empty cells must be 0; all scattered values are >= 0.
    cudaMemsetAsync(d_out, 0, (size_t)out_size * sizeof(float), 0);

    prep_kernel<<<1, 256>>>(
        (const float*)d_in[1],  (const float*)d_in[2],  (const float*)d_in[3],
        (const float*)d_in[4],  (const float*)d_in[5],  (const float*)d_in[6],
        (const float*)d_in[7],  (const float*)d_in[8],  (const float*)d_in[9],
        (const float*)d_in[10], (const float*)d_in[11], (const float*)d_in[12],
        (const float*)d_in[13], (const float*)d_in[14], (const float*)d_in[15],
        (const float*)d_in[16], (const float*)d_in[17], (const float*)d_in[18]);

    cudaFuncSetAttribute(point_kernel,
                         cudaFuncAttributeMaxDynamicSharedMemorySize, SMEM_BYTES);
    point_kernel<<<TOTPTS / 128, 128, SMEM_BYTES>>>(points, (float*)d_out);
}

// round 4
// speedup vs baseline: 1.0674x; 1.0664x over previous
#include <cuda_runtime.h>
#include <cuda_bf16.h>

#define NPTS   120000
#define BB     4
#define TOTPTS (BB * NPTS)
#define HH     128
#define WW     128
#define HW     (HH * WW)
#define FEAT   128

// Folded-parameter layout inside g_params / shared memory (float offsets)
#define OFF_W1T 0        // [4][64]    transposed, BN-folded
#define OFF_C1  256      // [64]
#define OFF_C2  320      // [128]
#define OFF_C3  448      // [128]
#define OFF_W2T 576      // [64][128]  transposed, BN-folded
#define OFF_W3T 8768     // [128][128] transposed, BN-folded
#define NPARAM  25152
#define SMEM_BYTES (NPARAM * 4)

#define THREADS 256

__device__ __align__(16) float g_params[NPARAM];

// ---- packed f32x2 helpers (FFMA2 — not emitted by ptxas from C++) ----------
typedef unsigned long long u64;

__device__ __forceinline__ u64 pk2(float lo, float hi) {
    u64 r;
    asm("mov.b64 %0, {%1, %2};" : "=l"(r) : "f"(lo), "f"(hi));
    return r;
}
__device__ __forceinline__ void upk2(u64 v, float& lo, float& hi) {
    asm("mov.b64 {%0, %1}, %2;" : "=f"(lo), "=f"(hi) : "l"(v));
}
__device__ __forceinline__ void fma2(u64& d, u64 a, u64 b) {
    asm("fma.rn.f32x2 %0, %1, %2, %0;" : "+l"(d) : "l"(a), "l"(b));
}

// ---------------------------------------------------------------------------
// Prep: fold BN (scale/shift) into weights & biases, transpose to [i][o].
// ---------------------------------------------------------------------------
__global__ void prep_kernel(
    const float* __restrict__ W1, const float* __restrict__ b1,
    const float* __restrict__ g1, const float* __restrict__ be1,
    const float* __restrict__ m1, const float* __restrict__ v1,
    const float* __restrict__ W2, const float* __restrict__ b2,
    const float* __restrict__ g2, const float* __restrict__ be2,
    const float* __restrict__ m2, const float* __restrict__ v2,
    const float* __restrict__ W3, const float* __restrict__ b3,
    const float* __restrict__ g3, const float* __restrict__ be3,
    const float* __restrict__ m3, const float* __restrict__ v3)
{
    const int t = threadIdx.x;
    for (int o = t; o < 64; o += blockDim.x) {
        float s = g1[o] * rsqrtf(v1[o] + 1e-5f);
        g_params[OFF_C1 + o] = (b1[o] - m1[o]) * s + be1[o];
        for (int i = 0; i < 4; i++)
            g_params[OFF_W1T + i * 64 + o] = W1[o * 4 + i] * s;
    }
    for (int o = t; o < 128; o += blockDim.x) {
        float s2 = g2[o] * rsqrtf(v2[o] + 1e-5f);
        g_params[OFF_C2 + o] = (b2[o] - m2[o]) * s2 + be2[o];
        for (int i = 0; i < 64; i++)
            g_params[OFF_W2T + i * 128 + o] = W2[o * 64 + i] * s2;
        float s3 = g3[o] * rsqrtf(v3[o] + 1e-5f);
        g_params[OFF_C3 + o] = (b3[o] - m3[o]) * s3 + be3[o];
        for (int i = 0; i < 128; i++)
            g_params[OFF_W3T + i * 128 + o] = W3[o * 128 + i] * s3;
    }
}

// ---------------------------------------------------------------------------
// Main: one thread = one point. Weights in SMEM (broadcast LDS.128),
// activations + accumulators entirely in registers (loops fully unrolled),
// packed fma.rn.f32x2 throughout. Scatter-max via int-aliased atomicMax.
// ---------------------------------------------------------------------------
__global__ __launch_bounds__(THREADS, 1)
void point_kernel(const float* __restrict__ points, float* __restrict__ out)
{
    extern __shared__ float sm[];
    const int tid = threadIdx.x;

    // Cooperative copy of folded params into SMEM
    {
        const float4* src = (const float4*)g_params;
        float4* dst = (float4*)sm;
        #pragma unroll 4
        for (int k = tid; k < NPARAM / 4; k += THREADS) dst[k] = src[k];
    }
    __syncthreads();

    const int g = blockIdx.x * THREADS + tid;
    const float4 p = ((const float4*)points)[g];

    const float xn = (p.x + 50.0f) / 100.0f;
    const float yn = (p.y + 50.0f) / 100.0f;
    if (!(xn >= 0.0f && xn <= 1.0f && yn >= 0.0f && yn <= 1.0f)) return;
    const int gx = min(WW - 1, (int)(xn * (float)(WW - 1)));
    const int gy = min(HH - 1, (int)(yn * (float)(HH - 1)));
    const int b  = g / NPTS;

    const float pa[4] = { p.x, p.y, p.z, p.w };

    // ---- Layer 1: 4 -> 64 (scalar, tiny) — activations a1 in registers ----
    float a1[64];
    #pragma unroll
    for (int o = 0; o < 64; o += 4) {
        float4 a = *(const float4*)(sm + OFF_C1 + o);
        #pragma unroll
        for (int i = 0; i < 4; i++) {
            const float4 w = *(const float4*)(sm + OFF_W1T + i * 64 + o);
            a.x = fmaf(w.x, pa[i], a.x);
            a.y = fmaf(w.y, pa[i], a.y);
            a.z = fmaf(w.z, pa[i], a.z);
            a.w = fmaf(w.w, pa[i], a.w);
        }
        a1[o + 0] = fmaxf(a.x, 0.0f);
        a1[o + 1] = fmaxf(a.y, 0.0f);
        a1[o + 2] = fmaxf(a.z, 0.0f);
        a1[o + 3] = fmaxf(a.w, 0.0f);
    }

    // ---- Layer 2: 64 -> 128, packed f32x2, fully unrolled ----
    u64 acc2[64];   // 128 outputs as 64 packed pairs
    {
        const ulonglong2* c2 = (const ulonglong2*)(sm + OFF_C2);
        #pragma unroll
        for (int k = 0; k < 32; k++) {
            ulonglong2 c = c2[k];
            acc2[2 * k] = c.x; acc2[2 * k + 1] = c.y;
        }
        #pragma unroll
        for (int i = 0; i < 64; i++) {
            const u64 aa = pk2(a1[i], a1[i]);
            const ulonglong2* w = (const ulonglong2*)(sm + OFF_W2T + i * 128);
            #pragma unroll
            for (int k = 0; k < 32; k++) {
                const ulonglong2 wv = w[k];
                fma2(acc2[2 * k],     wv.x, aa);
                fma2(acc2[2 * k + 1], wv.y, aa);
            }
        }
        // ReLU in place (packed pairs)
        #pragma unroll
        for (int k = 0; k < 64; k++) {
            float lo, hi; upk2(acc2[k], lo, hi);
            acc2[k] = pk2(fmaxf(lo, 0.0f), fmaxf(hi, 0.0f));
        }
    }

    // ---- Layer 3: 128 -> 128, two halves of 64 outputs (register budget) ----
    int* ob = (int*)out + b * (FEAT * HW) + gy * WW + gx;

    #pragma unroll 1
    for (int h = 0; h < 2; h++) {
        u64 acc3[32];   // 64 outputs as 32 packed pairs
        const ulonglong2* c3 = (const ulonglong2*)(sm + OFF_C3 + h * 64);
        #pragma unroll
        for (int k = 0; k < 16; k++) {
            ulonglong2 c = c3[k];
            acc3[2 * k] = c.x; acc3[2 * k + 1] = c.y;
        }
        const float* w3h = sm + OFF_W3T + h * 64;
        #pragma unroll
        for (int j = 0; j < 64; j++) {        // pairs of input indices i=2j, 2j+1
            float alo, ahi; upk2(acc2[j], alo, ahi);
            const u64 aa0 = pk2(alo, alo);
            const u64 aa1 = pk2(ahi, ahi);
            const ulonglong2* w0 = (const ulonglong2*)(w3h + (2 * j)     * 128);
            const ulonglong2* w1 = (const ulonglong2*)(w3h + (2 * j + 1) * 128);
            #pragma unroll
            for (int k = 0; k < 16; k++) {
                const ulonglong2 wv = w0[k];
                fma2(acc3[2 * k],     wv.x, aa0);
                fma2(acc3[2 * k + 1], wv.y, aa0);
            }
            #pragma unroll
            for (int k = 0; k < 16; k++) {
                const ulonglong2 wv = w1[k];
                fma2(acc3[2 * k],     wv.x, aa1);
                fma2(acc3[2 * k + 1], wv.y, aa1);
            }
        }
        // ReLU + scatter-max (skip zeros; all stored values >= 0)
        #pragma unroll
        for (int k = 0; k < 32; k++) {
            float lo, hi; upk2(acc3[k], lo, hi);
            const int o = h * 64 + 2 * k;
            if (lo > 0.0f) atomicMax(ob + (o    ) * HW, __float_as_int(lo));
            if (hi > 0.0f) atomicMax(ob + (o + 1) * HW, __float_as_int(hi));
        }
    }
}

// ---------------------------------------------------------------------------
extern "C" void kernel_launch(void* const* d_in, const int* in_sizes, int n_in,
                              void* d_out, int out_size)
{
    const float* points = (const float*)d_in[0];

    // Output init: empty cells must be 0; all scattered values are >= 0.
    cudaMemsetAsync(d_out, 0, (size_t)out_size * sizeof(float), 0);

    prep_kernel<<<1, 256>>>(
        (const float*)d_in[1],  (const float*)d_in[2],  (const float*)d_in[3],
        (const float*)d_in[4],  (const float*)d_in[5],  (const float*)d_in[6],
        (const float*)d_in[7],  (const float*)d_in[8],  (const float*)d_in[9],
        (const float*)d_in[10], (const float*)d_in[11], (const float*)d_in[12],
        (const float*)d_in[13], (const float*)d_in[14], (const float*)d_in[15],
        (const float*)d_in[16], (const float*)d_in[17], (const float*)d_in[18]);

    cudaFuncSetAttribute(point_kernel,
                         cudaFuncAttributeMaxDynamicSharedMemorySize, SMEM_BYTES);
    point_kernel<<<TOTPTS / THREADS, THREADS, SMEM_BYTES>>>(points, (float*)d_out);
}

// round 6
// speedup vs baseline: 1.6457x; 1.5418x over previous
#include <cuda_runtime.h>
#include <cuda_bf16.h>

#define NPTS   120000
#define BB     4
#define TOTPTS (BB * NPTS)
#define HH     128
#define WW     128
#define HW     (HH * WW)
#define FEAT   128

// Folded-parameter layout (float offsets), identical in g_params and SMEM
#define OFF_W1T 0        // [4][64]    transposed, BN-folded
#define OFF_C1  256      // [64]
#define OFF_C2  320      // [128]
#define OFF_C3  448      // [128]
#define OFF_W2T 576      // [64][128]  k-major, BN-folded
#define OFF_W3T 8768     // [128][128] k-major, BN-folded
#define NPARAM  25152

// SMEM activation staging
#define ACT1   25152               // [64][128]  layer-1 output, [k][pt]
#define ACT2   (ACT1 + 64 * 128)   // [128][128] layer-2 output, [out][pt], XOR-8 swizizzled
#define CELLS  (ACT2 + 128 * 128)  // [128] int cell indices (-1 = dead)
#define SMEM_FLOATS (CELLS + 128)
#define SMEM_BYTES  (SMEM_FLOATS * 4)

#define THREADS 256
#define PTILE   128
#define NTILES  (TOTPTS / PTILE)   // 3750

__device__ __align__(16) float  g_params[NPARAM];
__device__ __align__(16) float4 g_pts[TOTPTS];
__device__ int                  g_cell[TOTPTS];
__device__ int                  g_count;

typedef unsigned long long u64;

__device__ __forceinline__ u64 pk2(float lo, float hi) {
    u64 r; asm("mov.b64 %0, {%1, %2};" : "=l"(r) : "f"(lo), "f"(hi)); return r;
}
__device__ __forceinline__ void upk2(u64 v, float& lo, float& hi) {
    asm("mov.b64 {%0, %1}, %2;" : "=f"(lo), "=f"(hi) : "l"(v));
}
__device__ __forceinline__ void fma2(u64& d, u64 a, u64 b) {
    asm("fma.rn.f32x2 %0, %1, %2, %0;" : "+l"(d) : "l"(a), "l"(b));
}

// ---------------------------------------------------------------------------
// Prep: fold BN into weights & biases, transpose to [k][out].
// ---------------------------------------------------------------------------
__global__ void prep_kernel(
    const float* __restrict__ W1, const float* __restrict__ b1,
    const float* __restrict__ g1, const float* __restrict__ be1,
    const float* __restrict__ m1, const float* __restrict__ v1,
    const float* __restrict__ W2, const float* __restrict__ b2,
    const float* __restrict__ g2, const float* __restrict__ be2,
    const float* __restrict__ m2, const float* __restrict__ v2,
    const float* __restrict__ W3, const float* __restrict__ b3,
    const float* __restrict__ g3, const float* __restrict__ be3,
    const float* __restrict__ m3, const float* __restrict__ v3)
{
    const int t = threadIdx.x;
    for (int o = t; o < 64; o += blockDim.x) {
        float s = g1[o] * rsqrtf(v1[o] + 1e-5f);
        g_params[OFF_C1 + o] = (b1[o] - m1[o]) * s + be1[o];
        for (int i = 0; i < 4; i++)
            g_params[OFF_W1T + i * 64 + o] = W1[o * 4 + i] * s;
    }
    for (int o = t; o < 128; o += blockDim.x) {
        float s2 = g2[o] * rsqrtf(v2[o] + 1e-5f);
        g_params[OFF_C2 + o] = (b2[o] - m2[o]) * s2 + be2[o];
        for (int i = 0; i < 64; i++)
            g_params[OFF_W2T + i * 128 + o] = W2[o * 64 + i] * s2;
        float s3 = g3[o] * rsqrtf(v3[o] + 1e-5f);
        g_params[OFF_C3 + o] = (b3[o] - m3[o]) * s3 + be3[o];
        for (int i = 0; i < 128; i++)
            g_params[OFF_W3T + i * 128 + o] = W3[o * 128 + i] * s3;
    }
}

// ---------------------------------------------------------------------------
// Compaction: keep only in-range points; precompute BEV cell index.
// Warp-aggregated atomicAdd. Output order is nondeterministic but the final
// result (scatter-max) is order-invariant.
// ---------------------------------------------------------------------------
__global__ void compact_kernel(const float4* __restrict__ pts)
{
    const int g = blockIdx.x * 256 + threadIdx.x;
    const float4 p = pts[g];
    const float xn = (p.x + 50.0f) / 100.0f;
    const float yn = (p.y + 50.0f) / 100.0f;
    const bool valid = (xn >= 0.0f && xn <= 1.0f && yn >= 0.0f && yn <= 1.0f);

    const unsigned mask = __ballot_sync(0xffffffffu, valid);
    if (mask == 0u) return;
    const int lane = threadIdx.x & 31;
    const int leader = __ffs(mask) - 1;
    int base = 0;
    if (lane == leader) base = atomicAdd(&g_count, __popc(mask));
    base = __shfl_sync(0xffffffffu, base, leader);
    if (valid) {
        const int pos = base + __popc(mask & ((1u << lane) - 1u));
        const int gx = min(WW - 1, (int)(xn * (float)(WW - 1)));
        const int gy = min(HH - 1, (int)(yn * (float)(HH - 1)));
        const int b  = g / NPTS;
        g_pts[pos]  = p;
        g_cell[pos] = b * (FEAT * HW) + gy * WW + gx;
    }
}

// ---------------------------------------------------------------------------
// Register-blocked GEMM tile: C[8 pts][8 outs] per thread.
// sA: [KLEN][128] activation rows (pre-offset by ty*8 via caller pointer math
//     done per-k with optional swizzle), sB: [KLEN][128] weight rows + tx*8.
// ---------------------------------------------------------------------------
template <int KLEN, bool SWZ_A>
__device__ __forceinline__ void gemm_tile(
    const float* __restrict__ sA,   // base of [KLEN][128] activations
    const float* __restrict__ sB,   // base of [KLEN][128] weights, + tx*8
    const float* __restrict__ bias, // + tx*8
    int ty8,                        // ty*8 (A column base)
    float cf[8][8])
{
    u64 cc[8][4];
    {
        const ulonglong2 bz0 = *(const ulonglong2*)(bias);
        const ulonglong2 bz1 = *(const ulonglong2*)(bias + 4);
        #pragma unroll
        for (int i = 0; i < 8; i++) {
            cc[i][0] = bz0.x; cc[i][1] = bz0.y; cc[i][2] = bz1.x; cc[i][3] = bz1.y;
        }
    }
    #pragma unroll 4
    for (int k = 0; k < KLEN; k++) {
        const int acol = SWZ_A ? (ty8 ^ (((k >> 3) & 3) << 3)) : ty8;
        const float* A = sA + k * 128 + acol;
        const float* B = sB + k * 128;
        const float4 a0 = *(const float4*)A;
        const float4 a1 = *(const float4*)(A + 4);
        const ulonglong2 b0 = *(const ulonglong2*)B;
        const ulonglong2 b1 = *(const ulonglong2*)(B + 4);
        const float av[8] = { a0.x, a0.y, a0.z, a0.w, a1.x, a1.y, a1.z, a1.w };
        #pragma unroll
        for (int i = 0; i < 8; i++) {
            const u64 s = pk2(av[i], av[i]);
            fma2(cc[i][0], b0.x, s);
            fma2(cc[i][1], b0.y, s);
            fma2(cc[i][2], b1.x, s);
            fma2(cc[i][3], b1.y, s);
        }
    }
    #pragma unroll
    for (int i = 0; i < 8; i++)
        #pragma unroll
        for (int jp = 0; jp < 4; jp++)
            upk2(cc[i][jp], cf[i][2 * jp], cf[i][2 * jp + 1]);
}

// ---------------------------------------------------------------------------
// Main: one CTA = 128 compacted points x 128 features, tiled GEMM.
// ---------------------------------------------------------------------------
__global__ __launch_bounds__(THREADS, 1)
void point_kernel(float* __restrict__ out)
{
    const int count = g_count;
    const int tile  = blockIdx.x;
    if (tile * PTILE >= count) return;

    extern __shared__ float sm[];
    const int tid = threadIdx.x;

    // Cooperative copy of folded params into SMEM
    {
        const float4* src = (const float4*)g_params;
        float4* dst = (float4*)sm;
        #pragma unroll 4
        for (int k = tid; k < NPARAM / 4; k += THREADS) dst[k] = src[k];
    }
    __syncthreads();

    const int valid_n = min(PTILE, count - tile * PTILE);
    int* cellsm = (int*)(sm + CELLS);

    // ---- Layer 1: 4 -> 64, two threads per point, store act1[k][pt] ----
    {
        const int pt   = tid & 127;
        const int half = tid >> 7;
        const bool live = pt < valid_n;
        float4 p = make_float4(0.f, 0.f, 0.f, 0.f);
        if (live) p = g_pts[tile * PTILE + pt];
        if (half == 0) cellsm[pt] = live ? g_cell[tile * PTILE + pt] : -1;

        const float pa[4] = { p.x, p.y, p.z, p.w };
        const int ob = half * 32;
        #pragma unroll
        for (int o = 0; o < 32; o += 4) {
            float4 a = *(const float4*)(sm + OFF_C1 + ob + o);
            #pragma unroll
            for (int i = 0; i < 4; i++) {
                const float4 w = *(const float4*)(sm + OFF_W1T + i * 64 + ob + o);
                a.x = fmaf(w.x, pa[i], a.x);
                a.y = fmaf(w.y, pa[i], a.y);
                a.z = fmaf(w.z, pa[i], a.z);
                a.w = fmaf(w.w, pa[i], a.w);
            }
            sm[ACT1 + (ob + o + 0) * 128 + pt] = fmaxf(a.x, 0.0f);
            sm[ACT1 + (ob + o + 1) * 128 + pt] = fmaxf(a.y, 0.0f);
            sm[ACT1 + (ob + o + 2) * 128 + pt] = fmaxf(a.z, 0.0f);
            sm[ACT1 + (ob + o + 3) * 128 + pt] = fmaxf(a.w, 0.0f);
        }
    }
    __syncthreads();

    const int tx = tid & 15;       // output tile:  cols tx*8 .. tx*8+8
    const int ty = tid >> 4;       // point tile:   rows ty*8 .. ty*8+8
    const int ty8 = ty * 8;
    const int tx8 = tx * 8;

    // ---- Layer 2: [128 x 64] x [64 x 128], write act2[out][pt] swizzled ----
    {
        float cf[8][8];
        gemm_tile<64, false>(sm + ACT1, sm + OFF_W2T + tx8, sm + OFF_C2 + tx8, ty8, cf);
        // ReLU + transposed store: row r = tx8+j, swizzle col base by (r>>3)&3 == tx&3
        const int swz = (tx & 3) << 3;
        const int colb = ty8 ^ swz;
        #pragma unroll
        for (int j = 0; j < 8; j++) {
            float* dst = sm + ACT2 + (tx8 + j) * 128 + colb;
            const float4 v0 = make_float4(fmaxf(cf[0][j], 0.f), fmaxf(cf[1][j], 0.f),
                                          fmaxf(cf[2][j], 0.f), fmaxf(cf[3][j], 0.f));
            const float4 v1 = make_float4(fmaxf(cf[4][j], 0.f), fmaxf(cf[5][j], 0.f),
                                          fmaxf(cf[6][j], 0.f), fmaxf(cf[7][j], 0.f));
            *(float4*)(dst)     = v0;
            *(float4*)(dst + 4) = v1;
        }
    }
    __syncthreads();

    // ---- Layer 3: [128 x 128] x [128 x 128], swizzled A reads ----
    {
        float cf[8][8];
        gemm_tile<128, true>(sm + ACT2, sm + OFF_W3T + tx8, sm + OFF_C3 + tx8, ty8, cf);

        // ReLU + scatter-max (skip zeros and dead points)
        #pragma unroll
        for (int i = 0; i < 8; i++) {
            const int cell = cellsm[ty8 + i];
            if (cell < 0) continue;
            int* ob = (int*)out + cell;
            #pragma unroll
            for (int j = 0; j < 8; j++) {
                const float v = cf[i][j];
                if (v > 0.0f) atomicMax(ob + (tx8 + j) * HW, __float_as_int(v));
            }
        }
    }
}

// ---------------------------------------------------------------------------
extern "C" void kernel_launch(void* const* d_in, const int* in_sizes, int n_in,
                              void* d_out, int out_size)
{
    const float* points = (const float*)d_in[0];

    cudaMemsetAsync(d_out, 0, (size_t)out_size * sizeof(float), 0);

    int* dcnt = nullptr;
    cudaGetSymbolAddress((void**)&dcnt, g_count);
    cudaMemsetAsync(dcnt, 0, sizeof(int), 0);

    prep_kernel<<<1, 256>>>(
        (const float*)d_in[1],  (const float*)d_in[2],  (const float*)d_in[3],
        (const float*)d_in[4],  (const float*)d_in[5],  (const float*)d_in[6],
        (const float*)d_in[7],  (const float*)d_in[8],  (const float*)d_in[9],
        (const float*)d_in[10], (const float*)d_in[11], (const float*)d_in[12],
        (const float*)d_in[13], (const float*)d_in[14], (const float*)d_in[15],
        (const float*)d_in[16], (const float*)d_in[17], (const float*)d_in[18]);

    compact_kernel<<<TOTPTS / 256, 256>>>((const float4*)points);

    cudaFuncSetAttribute(point_kernel,
                         cudaFuncAttributeMaxDynamicSharedMemorySize, SMEM_BYTES);
    point_kernel<<<NTILES, THREADS, SMEM_BYTES>>>((float*)d_out);
}

// round 14
// speedup vs baseline: 3.2569x; 1.9790x over previous
#include <cuda_runtime.h>
#include <cuda_bf16.h>
#include <cstdint>

#define NPTS   120000
#define BB     4
#define TOTPTS (BB * NPTS)
#define HH     128
#define WW     128
#define HW     (HH * WW)
#define FEAT   128

#define THREADS 256
#define PTILE   128
#define NTILES  (TOTPTS / PTILE)   // 3750

// ---- SMEM layout (u32 offsets) ---------------------------------------------
// Fragment "blobs": per m16n8k8 tile, 32 lanes store their regs contiguously.
// A-blob = [lane][4] u32 (a0..a3), B-blob = [lane][2] u32 (b0,b1).
// tf32 frag maps (g = lane>>2, t = lane&3):
//   A: a0=(g,t) a1=(g+8,t) a2=(g,t+4) a3=(g+8,t+4)
//   B: b0=(k=t,n=g) b1=(k=t+4,n=g)
//   C: c0=(g,2t) c1=(g,2t+1) c2=(g+8,2t) c3=(g+8,2t+1)
#define SW2B   0                     // W2 blobs: 8 kt x 16 nt x 64 u32 = 8192
#define SW3B   8192                  // W3 blobs: 16 kt x 16 nt x 64 = 16384
#define SA1    24576                 // A1 blobs: 8 kt x 8 mt x 128 = 8192
#define SA2    32768                 // A2 blobs: 16 kt x 8 mt x 128 = 16384
#define SSMALL 49152                 // f32: W1T[4][64] | C1[64] | C2[128] | C3[128]
#define OFF_W1T 0
#define OFF_C1  256
#define OFF_C2  320
#define OFF_C3  448
#define NSMALL  576
#define SPTS   (SSMALL + NSMALL)     // 128 x float4 = 512 u32
#define SCELL  (SPTS + 512)          // 128 int
#define SMEM_U32 (SCELL + 128)
#define SMEM_BYTES (SMEM_U32 * 4)    // ~197 KB -> 1 CTA/SM

__device__ __align__(16) uint32_t g_w2b[8192];
__device__ __align__(16) uint32_t g_w3b[16384];
__device__ __align__(16) float    g_small[NSMALL];
__device__ __align__(16) float4   g_pts[TOTPTS];
__device__ int                    g_cell[TOTPTS];
__device__ int                    g_count;

__device__ __forceinline__ uint32_t cvt_tf32(float x) {
    uint32_t r; asm("cvt.rna.tf32.f32 %0, %1;" : "=r"(r) : "f"(x)); return r;
}
__device__ __forceinline__ void mma8(float* c, const uint4 a, const uint2 b) {
    asm volatile(
        "mma.sync.aligned.m16n8k8.row.col.f32.tf32.tf32.f32 "
        "{%0,%1,%2,%3}, {%4,%5,%6,%7}, {%8,%9}, {%0,%1,%2,%3};"
        : "+f"(c[0]), "+f"(c[1]), "+f"(c[2]), "+f"(c[3])
        : "r"(a.x), "r"(a.y), "r"(a.z), "r"(a.w), "r"(b.x), "r"(b.y));
}

// ---------------------------------------------------------------------------
// Prep: fold BN into weights, tf32, pack into B-frag blob order.
// grid = 128 (o = output/n), block = 128 (i = k).
// B-frag: element (k=i, n=o) -> lane = (o&7)*4 + ((i&7)&3), reg = (i&7)>>2.
// ---------------------------------------------------------------------------
__global__ void prep_kernel(
    const float* __restrict__ W1, const float* __restrict__ b1,
    const float* __restrict__ g1, const float* __restrict__ be1,
    const float* __restrict__ m1, const float* __restrict__ v1,
    const float* __restrict__ W2, const float* __restrict__ b2,
    const float* __restrict__ g2, const float* __restrict__ be2,
    const float* __restrict__ m2, const float* __restrict__ v2,
    const float* __restrict__ W3, const float* __restrict__ b3,
    const float* __restrict__ g3, const float* __restrict__ be3,
    const float* __restrict__ m3, const float* __restrict__ v3)
{
    const int o = blockIdx.x;      // n
    const int i = threadIdx.x;     // k

    const float s2 = g2[o] * rsqrtf(v2[o] + 1e-5f);
    const float s3 = g3[o] * rsqrtf(v3[o] + 1e-5f);

    const int nt   = o >> 3;
    const int kt   = i >> 3;
    const int lane = (o & 7) * 4 + ((i & 7) & 3);
    const int reg  = (i & 7) >> 2;

    if (i < 64)
        g_w2b[((kt * 16 + nt) * 32 + lane) * 2 + reg] = cvt_tf32(W2[o * 64 + i] * s2);
    g_w3b[((kt * 16 + nt) * 32 + lane) * 2 + reg] = cvt_tf32(W3[o * 128 + i] * s3);

    if (i == 0) {
        g_small[OFF_C2 + o] = (b2[o] - m2[o]) * s2 + be2[o];
        g_small[OFF_C3 + o] = (b3[o] - m3[o]) * s3 + be3[o];
        if (o < 64) {
            const float s1 = g1[o] * rsqrtf(v1[o] + 1e-5f);
            g_small[OFF_C1 + o] = (b1[o] - m1[o]) * s1 + be1[o];
            #pragma unroll
            for (int k = 0; k < 4; k++)
                g_small[OFF_W1T + k * 64 + o] = W1[o * 4 + k] * s1;
        }
    }
}

// ---------------------------------------------------------------------------
// Compaction: keep in-range points; precompute BEV cell index.
// ---------------------------------------------------------------------------
__global__ void compact_kernel(const float4* __restrict__ pts)
{
    const int g = blockIdx.x * 256 + threadIdx.x;
    const float4 p = pts[g];
    const float xn = (p.x + 50.0f) / 100.0f;
    const float yn = (p.y + 50.0f) / 100.0f;
    const bool valid = (xn >= 0.0f && xn <= 1.0f && yn >= 0.0f && yn <= 1.0f);

    const unsigned mask = __ballot_sync(0xffffffffu, valid);
    if (mask == 0u) return;
    const int lane = threadIdx.x & 31;
    const int leader = __ffs(mask) - 1;
    int base = 0;
    if (lane == leader) base = atomicAdd(&g_count, __popc(mask));
    base = __shfl_sync(0xffffffffu, base, leader);
    if (valid) {
        const int pos = base + __popc(mask & ((1u << lane) - 1u));
        const int gx = min(WW - 1, (int)(xn * (float)(WW - 1)));
        const int gy = min(HH - 1, (int)(yn * (float)(HH - 1)));
        const int b  = g / NPTS;
        g_pts[pos]  = p;
        g_cell[pos] = b * (FEAT * HW) + gy * WW + gx;
    }
}

// ---------------------------------------------------------------------------
// Main: 1 CTA = 128 pts x 128 feats. 8 warps; warp (mr = w%4, nc = w/4)
// owns pts [mr*32,+32) x outs [nc*64,+64).
// ---------------------------------------------------------------------------
__global__ __launch_bounds__(THREADS, 1)
void point_kernel(float* __restrict__ out)
{
    const int count = g_count;
    const int tile  = blockIdx.x;
    if (tile * PTILE >= count) return;

    extern __shared__ __align__(16) uint32_t sm[];
    const int tid  = threadIdx.x;
    const int w    = tid >> 5;
    const int lane = tid & 31;
    const int lq   = lane >> 2;       // g: row within half-tile
    const int lr   = lane & 3;        // t: k/n selector

    // ---- Copy weights/params; stage points + cells ----
    {
        uint4* dst = (uint4*)sm;
        const uint4* s2 = (const uint4*)g_w2b;
        const uint4* s3 = (const uint4*)g_w3b;
        #pragma unroll 2
        for (int k = tid; k < 8192 / 4; k += THREADS)  dst[SW2B / 4 + k] = s2[k];
        #pragma unroll 4
        for (int k = tid; k < 16384 / 4; k += THREADS) dst[SW3B / 4 + k] = s3[k];
        for (int k = tid; k < NSMALL / 4; k += THREADS)
            dst[SSMALL / 4 + k] = ((const uint4*)g_small)[k];
    }
    const int valid_n = min(PTILE, count - tile * PTILE);
    if (tid < PTILE) {
        const bool live = tid < valid_n;
        ((float4*)(sm + SPTS))[tid] = live ? g_pts[tile * PTILE + tid]
                                           : make_float4(0.f, 0.f, 0.f, 0.f);
        ((int*)(sm + SCELL))[tid] = live ? g_cell[tile * PTILE + tid] : -1;
    }
    __syncthreads();

    const float*  smallf = (const float*)(sm + SSMALL);
    const float4* spts   = (const float4*)(sm + SPTS);
    const int*    scell  = (const int*)(sm + SCELL);

    // ---- Layer 1: 4 -> 64. Warp w = m-tile w. Thread computes its A-frag:
    //      rows (r0, r0+8), cols (kt*8+lr, kt*8+lr+4). ----
    {
        const int r0 = w * 16 + lq;
        const float4 P0 = spts[r0];
        const float4 P1 = spts[r0 + 8];
        #pragma unroll
        for (int kt = 0; kt < 8; kt++) {
            const int k0 = kt * 8 + lr;
            const int k1 = k0 + 4;
            float o00 = smallf[OFF_C1 + k0], o01 = smallf[OFF_C1 + k1];
            float o10 = o00, o11 = o01;
            #pragma unroll
            for (int i = 0; i < 4; i++) {
                const float wa = smallf[OFF_W1T + i * 64 + k0];
                const float wb = smallf[OFF_W1T + i * 64 + k1];
                const float p0i = (i == 0) ? P0.x : (i == 1) ? P0.y : (i == 2) ? P0.z : P0.w;
                const float p1i = (i == 0) ? P1.x : (i == 1) ? P1.y : (i == 2) ? P1.z : P1.w;
                o00 = fmaf(wa, p0i, o00);
                o01 = fmaf(wb, p0i, o01);
                o10 = fmaf(wa, p1i, o10);
                o11 = fmaf(wb, p1i, o11);
            }
            uint4 q;
            q.x = cvt_tf32(fmaxf(o00, 0.0f));   // a0 (r0,   k0)
            q.y = cvt_tf32(fmaxf(o10, 0.0f));   // a1 (r0+8, k0)
            q.z = cvt_tf32(fmaxf(o01, 0.0f));   // a2 (r0,   k1)
            q.w = cvt_tf32(fmaxf(o11, 0.0f));   // a3 (r0+8, k1)
            ((uint4*)(sm + SA1))[(kt * 8 + w) * 32 + lane] = q;
        }
    }
    __syncthreads();

    const int mr = w & 3;        // pts quadrant
    const int nc = w >> 2;       // outs half

    // ---- Layer 2: [128x64] x [64x128]^T, accum = bias (C cols 2lr,2lr+1) ----
    float c[2][8][4];
    #pragma unroll
    for (int j = 0; j < 8; j++) {
        const float2 bz = *(const float2*)(smallf + OFF_C2 + nc * 64 + j * 8 + 2 * lr);
        #pragma unroll
        for (int i = 0; i < 2; i++) {
            c[i][j][0] = bz.x; c[i][j][1] = bz.y; c[i][j][2] = bz.x; c[i][j][3] = bz.y;
        }
    }
    #pragma unroll
    for (int kt = 0; kt < 8; kt++) {
        const uint4 a0 = ((const uint4*)(sm + SA1))[(kt * 8 + 2 * mr    ) * 32 + lane];
        const uint4 a1 = ((const uint4*)(sm + SA1))[(kt * 8 + 2 * mr + 1) * 32 + lane];
        #pragma unroll
        for (int j = 0; j < 8; j++) {
            const uint2 b = ((const uint2*)(sm + SW2B))[(kt * 16 + nc * 8 + j) * 32 + lane];
            mma8(c[0][j], a0, b);
            mma8(c[1][j], a1, b);
        }
    }
    // Epilogue 2: ReLU + tf32, scatter C-frags into A-frag blob positions.
    // (c0,c2) = col 2lr  -> lane' = lq*4 + (2lr&3),     regs (base, base+1)
    // (c1,c3) = col 2lr+1-> lane''= lq*4 + ((2lr+1)&3), regs (base, base+1)
    // base = (lr < 2) ? 0 : 2.
    {
        const int baser = (lr < 2) ? 0 : 2;
        const int laneA = lq * 4 + ((2 * lr) & 3);
        const int laneB = lq * 4 + ((2 * lr + 1) & 3);
        #pragma unroll
        for (int i = 0; i < 2; i++) {
            const int mt = 2 * mr + i;
            #pragma unroll
            for (int j = 0; j < 8; j++) {
                const int fb = ((nc * 8 + j) * 8 + mt) * 32;   // frag base (u32 /4)
                const uint2 pa = make_uint2(cvt_tf32(fmaxf(c[i][j][0], 0.0f)),
                                            cvt_tf32(fmaxf(c[i][j][2], 0.0f)));
                const uint2 pb = make_uint2(cvt_tf32(fmaxf(c[i][j][1], 0.0f)),
                                            cvt_tf32(fmaxf(c[i][j][3], 0.0f)));
                *(uint2*)(sm + SA2 + (fb + laneA) * 4 + baser) = pa;
                *(uint2*)(sm + SA2 + (fb + laneB) * 4 + baser) = pb;
            }
        }
    }
    __syncthreads();

    // ---- Layer 3: [128x128] x [128x128]^T, accum = bias ----
    float d[2][8][4];
    #pragma unroll
    for (int j = 0; j < 8; j++) {
        const float2 bz = *(const float2*)(smallf + OFF_C3 + nc * 64 + j * 8 + 2 * lr);
        #pragma unroll
        for (int i = 0; i < 2; i++) {
            d[i][j][0] = bz.x; d[i][j][1] = bz.y; d[i][j][2] = bz.x; d[i][j][3] = bz.y;
        }
    }
    #pragma unroll
    for (int kt = 0; kt < 16; kt++) {
        const uint4 a0 = ((const uint4*)(sm + SA2))[(kt * 8 + 2 * mr    ) * 32 + lane];
        const uint4 a1 = ((const uint4*)(sm + SA2))[(kt * 8 + 2 * mr + 1) * 32 + lane];
        #pragma unroll
        for (int j = 0; j < 8; j++) {
            const uint2 b = ((const uint2*)(sm + SW3B))[(kt * 16 + nc * 8 + j) * 32 + lane];
            mma8(d[0][j], a0, b);
            mma8(d[1][j], a1, b);
        }
    }

    // ---- Epilogue 3: ReLU + scatter-max (C layout: rows lq/lq+8, cols 2lr/2lr+1) ----
    int* outp = (int*)out;
    #pragma unroll
    for (int i = 0; i < 2; i++) {
        const int r0 = (2 * mr + i) * 16 + lq;
        const int c0 = scell[r0];
        const int c1 = scell[r0 + 8];
        #pragma unroll
        for (int j = 0; j < 8; j++) {
            const int n0 = (nc * 64 + j * 8 + 2 * lr) * HW;
            const float v0 = d[i][j][0], v1 = d[i][j][1];
            const float v2 = d[i][j][2], v3 = d[i][j][3];
            if (c0 >= 0) {
                if (v0 > 0.0f) atomicMax(outp + c0 + n0,      __float_as_int(v0));
                if (v1 > 0.0f) atomicMax(outp + c0 + n0 + HW, __float_as_int(v1));
            }
            if (c1 >= 0) {
                if (v2 > 0.0f) atomicMax(outp + c1 + n0,      __float_as_int(v2));
                if (v3 > 0.0f) atomicMax(outp + c1 + n0 + HW, __float_as_int(v3));
            }
        }
    }
}

// ---------------------------------------------------------------------------
extern "C" void kernel_launch(void* const* d_in, const int* in_sizes, int n_in,
                              void* d_out, int out_size)
{
    const float* points = (const float*)d_in[0];

    cudaMemsetAsync(d_out, 0, (size_t)out_size * sizeof(float), 0);

    int* dcnt = nullptr;
    cudaGetSymbolAddress((void**)&dcnt, g_count);
    cudaMemsetAsync(dcnt, 0, sizeof(int), 0);

    prep_kernel<<<128, 128>>>(
        (const float*)d_in[1],  (const float*)d_in[2],  (const float*)d_in[3],
        (const float*)d_in[4],  (const float*)d_in[5],  (const float*)d_in[6],
        (const float*)d_in[7],  (const float*)d_in[8],  (const float*)d_in[9],
        (const float*)d_in[10], (const float*)d_in[11], (const float*)d_in[12],
        (const float*)d_in[13], (const float*)d_in[14], (const float*)d_in[15],
        (const float*)d_in[16], (const float*)d_in[17], (const float*)d_in[18]);

    compact_kernel<<<TOTPTS / 256, 256>>>((const float4*)points);

    cudaFuncSetAttribute(point_kernel,
                         cudaFuncAttributeMaxDynamicSharedMemorySize, SMEM_BYTES);
    point_kernel<<<NTILES, THREADS, SMEM_BYTES>>>((float*)d_out);
}